// round 3
// baseline (speedup 1.0000x reference)
#include <cuda_runtime.h>

// FocalLoss: loss = sum_b mean_a [ w[a] * (1-p)^2 * BCE(clamp(p), t) ]
// inputs [B, A] f32, targets [A, B] i32 (0/1), w [A] f32 -> scalar f32
// Single-kernel: per-block partials + last-block-done final reduction.
constexpr int BVAL = 1000000;
constexpr int AVAL = 40;
constexpr float EPSF = 1e-12f;
constexpr int TPB = 256;
constexpr int GRID = (BVAL + TPB - 1) / TPB;   // 3907

__device__ float g_partials[GRID];
__device__ unsigned int g_count;   // zero-init at load; self-resets via atomicInc wrap

__global__ void __launch_bounds__(TPB) focal_fused_kernel(
    const float* __restrict__ inputs,
    const int*   __restrict__ targets,
    const float* __restrict__ w,
    float* __restrict__ out)
{
    __shared__ float sw[AVAL];
    int tid = threadIdx.x;
    if (tid < AVAL) sw[tid] = w[tid];
    __syncthreads();

    int b = blockIdx.x * TPB + tid;
    float acc = 0.0f;
    if (b < BVAL) {
        const float4* row = reinterpret_cast<const float4*>(inputs + (long)b * AVAL);
        #pragma unroll
        for (int a4 = 0; a4 < AVAL / 4; a4++) {
            float4 p4 = __ldg(row + a4);
            float pv[4] = {p4.x, p4.y, p4.z, p4.w};
            #pragma unroll
            for (int j = 0; j < 4; j++) {
                int a = a4 * 4 + j;
                int t = __ldg(targets + (long)a * BVAL + b);  // coalesced per a
                float p  = pv[j];
                float pc = fminf(fmaxf(p, EPSF), 1.0f - EPSF);
                float arg = t ? pc : (1.0f - pc);   // t is 0/1: only one log needed
                float bce = -__logf(arg);           // MUFU.LG2: stays HBM-bound
                float om  = 1.0f - p;               // focal weight uses UNCLAMPED p
                acc = fmaf(sw[a] * om * om, bce, acc);
            }
        }
    }

    // intra-warp reduce
    #pragma unroll
    for (int off = 16; off; off >>= 1)
        acc += __shfl_down_sync(0xffffffffu, acc, off);

    __shared__ float warpsum[TPB / 32];
    if ((tid & 31) == 0) warpsum[tid >> 5] = acc;
    __syncthreads();

    __shared__ bool amLast;
    if (tid == 0) {
        float v = 0.0f;
        #pragma unroll
        for (int i = 0; i < TPB / 32; i++) v += warpsum[i];
        g_partials[blockIdx.x] = v;
        __threadfence();
        // wraps back to 0 when old == GRID-1 -> deterministic across graph replays
        unsigned int old = atomicInc(&g_count, GRID - 1);
        amLast = (old == GRID - 1);
    }
    __syncthreads();

    if (amLast) {
        double d = 0.0;
        for (int i = tid; i < GRID; i += TPB)
            d += (double)g_partials[i];
        // double shfl reduce within warp
        #pragma unroll
        for (int off = 16; off; off >>= 1)
            d += __shfl_down_sync(0xffffffffu, d, off);
        __shared__ double dws[TPB / 32];
        if ((tid & 31) == 0) dws[tid >> 5] = d;
        __syncthreads();
        if (tid == 0) {
            double tot = 0.0;
            #pragma unroll
            for (int i = 0; i < TPB / 32; i++) tot += dws[i];
            out[0] = (float)(tot * (1.0 / (double)AVAL));
        }
    }
}

extern "C" void kernel_launch(void* const* d_in, const int* in_sizes, int n_in,
                              void* d_out, int out_size)
{
    const float* inputs  = (const float*)d_in[0];   // [B, A]
    const int*   targets = (const int*)  d_in[1];   // [A, B]
    const float* weights = (const float*)d_in[2];   // [A]
    focal_fused_kernel<<<GRID, TPB>>>(inputs, targets, weights, (float*)d_out);
}